// round 4
// baseline (speedup 1.0000x reference)
#include <cuda_runtime.h>
#include <float.h>
#include <math.h>

// Problem constants
#define N_TOK   32768
#define DIM     512
#define NTYPE   26
#define PER     128
#define NCODE   (NTYPE*PER)     // 3328
#define SAMP    312             // 26 * 12
#define ND      (N_TOK*DIM)     // 16777216
#define TEMP    0.07f
#define COMMIT  0.25f
#define KC      32

// -------- scratch (device globals; no allocation allowed) --------
__device__ float  g_ne[NCODE*DIM];     // normalized embeddings
__device__ float  g_en2[NCODE];        // ||emb_j||^2
__device__ int    g_count[NTYPE];
__device__ int    g_offset[NTYPE];
__device__ int    g_cursor[NTYPE];
__device__ int    g_order[N_TOK];
__device__ int    g_work[512];         // (type<<8)|tile worklist
__device__ int    g_nwork;
__device__ int    g_ticket;
__device__ int    g_udone;
__device__ float  g_se[SAMP*DIM];
__device__ int    g_slab[SAMP];
__device__ double g_diff_acc;
__device__ double g_uloss_acc;

__device__ __forceinline__ void ffma2(unsigned long long &d,
                                      unsigned long long a,
                                      unsigned long long b) {
    asm("fma.rn.f32x2 %0, %1, %2, %0;" : "+l"(d) : "l"(a), "l"(b));
}
__device__ __forceinline__ float f2lo(unsigned long long v) {
    return __uint_as_float((unsigned)(v & 0xffffffffull));
}
__device__ __forceinline__ float f2hi(unsigned long long v) {
    return __uint_as_float((unsigned)(v >> 32));
}

// -------- kernels --------
__global__ void k_init() {
    int t = threadIdx.x;
    if (t < NTYPE) g_count[t] = 0;
    if (t == 0) { g_diff_acc = 0.0; g_uloss_acc = 0.0; g_ticket = 0; g_udone = 0; }
}

// block per code row: norm2 + normalized row
__global__ void k_norm_emb(const float* __restrict__ emb) {
    int row = blockIdx.x;
    int t = threadIdx.x;
    float4 a = ((const float4*)(emb + (size_t)row * DIM))[t];
    float s = a.x*a.x + a.y*a.y + a.z*a.z + a.w*a.w;
    #pragma unroll
    for (int o = 16; o; o >>= 1) s += __shfl_xor_sync(0xffffffffu, s, o);
    __shared__ float ws[4];
    if ((t & 31) == 0) ws[t >> 5] = s;
    __syncthreads();
    float tot = ws[0] + ws[1] + ws[2] + ws[3];
    if (t == 0) g_en2[row] = tot;
    float inv = 1.0f / fmaxf(sqrtf(tot), 1e-12f);
    float4 o4 = make_float4(a.x*inv, a.y*inv, a.z*inv, a.w*inv);
    ((float4*)(g_ne + (size_t)row * DIM))[t] = o4;
}

__global__ void k_hist(const int* __restrict__ Q) {
    __shared__ int h[NTYPE];
    if (threadIdx.x < NTYPE) h[threadIdx.x] = 0;
    __syncthreads();
    for (int i = blockIdx.x * blockDim.x + threadIdx.x; i < N_TOK;
         i += gridDim.x * blockDim.x)
        atomicAdd(&h[Q[i]], 1);
    __syncthreads();
    if (threadIdx.x < NTYPE && h[threadIdx.x])
        atomicAdd(&g_count[threadIdx.x], h[threadIdx.x]);
}

__global__ void k_scan() {
    int off = 0, nw = 0;
    for (int t = 0; t < NTYPE; t++) {
        g_offset[t] = off; g_cursor[t] = off;
        int c = g_count[t]; off += c;
        int tiles = (c + 127) / 128;
        for (int tt = 0; tt < tiles; tt++) g_work[nw++] = (t << 8) | tt;
    }
    g_nwork = nw;
}

__global__ void k_scatter(const int* __restrict__ Q) {
    __shared__ int loc[NTYPE], base[NTYPE];
    int tid = threadIdx.x;
    if (tid < NTYPE) loc[tid] = 0;
    __syncthreads();
    int per = (N_TOK + gridDim.x - 1) / gridDim.x;
    int s = blockIdx.x * per;
    int e = min(s + per, N_TOK);
    for (int i = s + tid; i < e; i += blockDim.x)
        atomicAdd(&loc[Q[i]], 1);
    __syncthreads();
    if (tid < NTYPE) { base[tid] = atomicAdd(&g_cursor[tid], loc[tid]); loc[tid] = 0; }
    __syncthreads();
    for (int i = s + tid; i < e; i += blockDim.x) {
        int t = Q[i];
        g_order[base[t] + atomicAdd(&loc[t], 1)] = i;
    }
}

// Persistent FFMA2 GEMM + fused row-norm + argmin + commit-loss + idx-tail
// + fused output-row copy (out row = g_ne[winning code]).
__global__ __launch_bounds__(256, 2) void k_argmin(const float* __restrict__ x,
                                                   const float* __restrict__ emb,
                                                   float* __restrict__ out) {
    __shared__ __align__(16) float As[KC][256];   // duplicated tokens: (a_i,a_i) pairs
    __shared__ __align__(16) float Bs[KC][128];   // codes, k-major
    __shared__ int   toks[128];
    __shared__ float snorm[128];
    __shared__ float sen2[128];
    __shared__ int   scodes[128];
    __shared__ int   s_work;
    __shared__ float red[256];

    int tid = threadIdx.x;
    int tx = tid & 15;       // j dimension (pairs 2tx+32s)
    int ty = tid >> 4;       // i dimension (8ty + r)
    int fr = tid >> 1;       // fill row 0..127
    int fq = tid & 1;        // fill k-half (16 floats each)
    float local_loss = 0.0f;

    for (;;) {
        if (tid == 0) s_work = atomicAdd(&g_ticket, 1);
        __syncthreads();
        int w = s_work;
        if (w >= g_nwork) break;
        int wk   = g_work[w];
        int type = wk >> 8;
        int row0 = (wk & 255) * 128;
        int cnt  = g_count[type];
        int rows = min(128, cnt - row0);

        if (tid < 128) {
            int r = (tid < rows) ? tid : (rows - 1);
            toks[tid]  = g_order[g_offset[type] + row0 + r];
            snorm[tid] = 0.0f;
            sen2[tid]  = g_en2[type * PER + tid];
        }
        __syncthreads();

        const float* xrow = x   + (size_t)toks[fr] * DIM + fq * 16;
        const float* brow = emb + (size_t)(type * PER + fr) * DIM + fq * 16;

        unsigned long long acc[8][4];
        #pragma unroll
        for (int r = 0; r < 8; r++)
            #pragma unroll
            for (int s = 0; s < 4; s++) acc[r][s] = 0ull;   // (0.f,0.f)

        for (int k0 = 0; k0 < DIM; k0 += KC) {
            // --- fill A (duplicated) + accumulate row sumsq ---
            float ps = 0.0f;
            #pragma unroll
            for (int u = 0; u < 4; u++) {
                float4 v = *(const float4*)(xrow + k0 + 4 * u);
                ps += v.x*v.x + v.y*v.y + v.z*v.z + v.w*v.w;
                int kb = fq * 16 + 4 * u;
                *(float2*)&As[kb+0][2*fr] = make_float2(v.x, v.x);
                *(float2*)&As[kb+1][2*fr] = make_float2(v.y, v.y);
                *(float2*)&As[kb+2][2*fr] = make_float2(v.z, v.z);
                *(float2*)&As[kb+3][2*fr] = make_float2(v.w, v.w);
            }
            atomicAdd(&snorm[fr], ps);
            // --- fill B ---
            #pragma unroll
            for (int u = 0; u < 4; u++) {
                float4 v = *(const float4*)(brow + k0 + 4 * u);
                int kb = fq * 16 + 4 * u;
                Bs[kb+0][fr] = v.x; Bs[kb+1][fr] = v.y;
                Bs[kb+2][fr] = v.z; Bs[kb+3][fr] = v.w;
            }
            __syncthreads();

            // --- FFMA2 inner ---
            #pragma unroll 4
            for (int k = 0; k < KC; k++) {
                const ulonglong2* Ar = (const ulonglong2*)&As[k][0]; // 64 per row
                const unsigned long long* Br = (const unsigned long long*)&Bs[k][0]; // 64/row
                ulonglong2 A0 = Ar[4*ty + 0];
                ulonglong2 A1 = Ar[4*ty + 1];
                ulonglong2 A2 = Ar[4*ty + 2];
                ulonglong2 A3 = Ar[4*ty + 3];
                unsigned long long av[8] = {A0.x, A0.y, A1.x, A1.y,
                                            A2.x, A2.y, A3.x, A3.y};
                unsigned long long bv[4];
                #pragma unroll
                for (int s = 0; s < 4; s++) bv[s] = Br[tx + 16*s];
                #pragma unroll
                for (int r = 0; r < 8; r++)
                    #pragma unroll
                    for (int s = 0; s < 4; s++)
                        ffma2(acc[r][s], av[r], bv[s]);
            }
            __syncthreads();
        }

        // --- epilogue: argmin + loss + idx tail ---
        #pragma unroll
        for (int r = 0; r < 8; r++) {
            int m = 8 * ty + r;
            float invn = 1.0f / fmaxf(sqrtf(snorm[m]), 1e-12f);
            float best = FLT_MAX; int bc = 1 << 30;
            #pragma unroll
            for (int s = 0; s < 4; s++) {
                int j0 = 2 * tx + 32 * s;
                float sc0 = sen2[j0]   - 2.0f * invn * f2lo(acc[r][s]);
                float sc1 = sen2[j0+1] - 2.0f * invn * f2hi(acc[r][s]);
                if (sc0 < best || (sc0 == best && j0 < bc))   { best = sc0; bc = j0; }
                if (sc1 < best || (sc1 == best && j0+1 < bc)) { best = sc1; bc = j0+1; }
            }
            #pragma unroll
            for (int o = 8; o; o >>= 1) {
                float s2 = __shfl_xor_sync(0xffffffffu, best, o);
                int   c2 = __shfl_xor_sync(0xffffffffu, bc,   o);
                if (s2 < best || (s2 == best && c2 < bc)) { best = s2; bc = c2; }
            }
            if (tx == 0 && m < rows) {
                int tok  = toks[m];
                int code = type * PER + bc;
                scodes[m] = code;
                out[ND + 2 + tok] = (float)code;
                float e2 = sen2[bc];
                // ||q - xn||^2 = 2 - (e2 - best)/sqrt(e2)
                local_loss += 2.0f - (e2 - best) / sqrtf(e2);
            }
        }
        __syncthreads();

        // --- fused finalize: out row = g_ne[code] ---
        if (fr < rows) {
            const float4* src = (const float4*)(g_ne + (size_t)scodes[fr] * DIM) + fq * 64;
            float4*       dst = (float4*)(out + (size_t)toks[fr] * DIM) + fq * 64;
            #pragma unroll 8
            for (int q = 0; q < 64; q++) dst[q] = src[q];
        }
        // loop-top __syncthreads orders copy before smem reuse
    }

    red[tid] = local_loss;
    __syncthreads();
    for (int s = 128; s; s >>= 1) {
        if (tid < s) red[tid] += red[tid + s];
        __syncthreads();
    }
    if (tid == 0 && red[0] != 0.0f) atomicAdd(&g_diff_acc, (double)red[0]);
}

__global__ void k_gather_se(const int* __restrict__ samp) {
    int b = blockIdx.x;
    int s = samp[b];
    int t = threadIdx.x;
    ((float4*)(g_se + (size_t)b * DIM))[t] =
        ((const float4*)(g_ne + (size_t)s * DIM))[t];
    if (t == 0) g_slab[b] = s / PER;
}

__global__ __launch_bounds__(256) void k_uloss(float* __restrict__ out) {
    int i = blockIdx.x;
    __shared__ float si[DIM];
    __shared__ float wsum[8], wpos[8];
    int tid = threadIdx.x;
    if (tid < 128) ((float4*)si)[tid] = ((const float4*)(g_se + (size_t)i * DIM))[tid];
    __syncthreads();
    int lab_i = g_slab[i];
    int w = tid >> 5, lane = tid & 31;
    float sum = 0.0f, pos = 0.0f;
    for (int j = w; j < SAMP; j += 8) {
        const float* vj = g_se + (size_t)j * DIM;
        float p = 0.0f;
        #pragma unroll 4
        for (int d = lane; d < DIM; d += 32) p = fmaf(si[d], vj[d], p);
        #pragma unroll
        for (int o = 16; o; o >>= 1) p += __shfl_xor_sync(0xffffffffu, p, o);
        if (lane == 0 && j != i) {
            float e = expf(p / TEMP);
            sum += e;
            if (g_slab[j] == lab_i) pos += e;
        }
    }
    if (lane == 0) { wsum[w] = sum; wpos[w] = pos; }
    __syncthreads();
    if (tid == 0) {
        float S = 0.0f, P = 0.0f;
        #pragma unroll
        for (int k = 0; k < 8; k++) { S += wsum[k]; P += wpos[k]; }
        atomicAdd(&g_uloss_acc, (double)(-logf(P / S)));
        __threadfence();
        int d = atomicAdd(&g_udone, 1);
        if (d == SAMP - 1) {
            double u = atomicAdd(&g_uloss_acc, 0.0);
            out[ND]     = (float)((1.0 + (double)COMMIT) * g_diff_acc / (double)ND);
            out[ND + 1] = (float)(u / (double)SAMP);
        }
    }
}

// -------- launch --------
extern "C" void kernel_launch(void* const* d_in, const int* in_sizes, int n_in,
                              void* d_out, int out_size) {
    const float* x    = (const float*)d_in[0];
    const float* emb  = (const float*)d_in[1];
    const int*   Q    = (const int*)d_in[2];
    const int*   samp = (const int*)d_in[3];
    float* out = (float*)d_out;

    k_init<<<1, 32>>>();
    k_norm_emb<<<NCODE, 128>>>(emb);
    k_hist<<<64, 256>>>(Q);
    k_scan<<<1, 1>>>();
    k_scatter<<<64, 256>>>(Q);
    k_argmin<<<296, 256>>>(x, emb, out);
    k_gather_se<<<SAMP, 128>>>(samp);
    k_uloss<<<SAMP, 256>>>(out);
}

// round 5
// speedup vs baseline: 1.2086x; 1.2086x over previous
#include <cuda_runtime.h>
#include <float.h>
#include <math.h>

// Problem constants
#define N_TOK   32768
#define DIM     512
#define NTYPE   26
#define PER     128
#define NCODE   (NTYPE*PER)     // 3328
#define SAMP    312             // 26 * 12
#define ND      (N_TOK*DIM)     // 16777216
#define TEMP    0.07f
#define COMMIT  0.25f
#define KC      32

// -------- scratch (device globals; no allocation allowed) --------
__device__ float  g_ne[NCODE*DIM];     // normalized embeddings
__device__ float  g_en2[NCODE];        // ||emb_j||^2
__device__ int    g_count[NTYPE];
__device__ int    g_offset[NTYPE];
__device__ int    g_cursor[NTYPE];
__device__ int    g_order[N_TOK];
__device__ int    g_work[512];         // (type<<8)|tile worklist
__device__ int    g_nwork;
__device__ int    g_ticket;
__device__ int    g_udone;
__device__ float  g_se[SAMP*DIM];
__device__ int    g_slab[SAMP];
__device__ double g_diff_acc;
__device__ double g_uloss_acc;

// -------- kernels --------
__global__ void k_init() {
    int t = threadIdx.x;
    if (t < NTYPE) g_count[t] = 0;
    if (t == 0) { g_diff_acc = 0.0; g_uloss_acc = 0.0; g_ticket = 0; g_udone = 0; }
}

// block per code row: norm2 + normalized row
__global__ void k_norm_emb(const float* __restrict__ emb) {
    int row = blockIdx.x;
    int t = threadIdx.x;
    float4 a = ((const float4*)(emb + (size_t)row * DIM))[t];
    float s = a.x*a.x + a.y*a.y + a.z*a.z + a.w*a.w;
    #pragma unroll
    for (int o = 16; o; o >>= 1) s += __shfl_xor_sync(0xffffffffu, s, o);
    __shared__ float ws[4];
    if ((t & 31) == 0) ws[t >> 5] = s;
    __syncthreads();
    float tot = ws[0] + ws[1] + ws[2] + ws[3];
    if (t == 0) g_en2[row] = tot;
    float inv = 1.0f / fmaxf(sqrtf(tot), 1e-12f);
    float4 o4 = make_float4(a.x*inv, a.y*inv, a.z*inv, a.w*inv);
    ((float4*)(g_ne + (size_t)row * DIM))[t] = o4;
}

__global__ void k_hist(const int* __restrict__ Q) {
    __shared__ int h[NTYPE];
    if (threadIdx.x < NTYPE) h[threadIdx.x] = 0;
    __syncthreads();
    for (int i = blockIdx.x * blockDim.x + threadIdx.x; i < N_TOK;
         i += gridDim.x * blockDim.x)
        atomicAdd(&h[Q[i]], 1);
    __syncthreads();
    if (threadIdx.x < NTYPE && h[threadIdx.x])
        atomicAdd(&g_count[threadIdx.x], h[threadIdx.x]);
}

// one warp: shfl scans over counts and tile counts, cooperative worklist build
__global__ void k_scan() {
    int lane = threadIdx.x;
    int c = (lane < NTYPE) ? g_count[lane] : 0;
    int tiles = (c + 127) / 128;
    int sc = c, st = tiles;
    #pragma unroll
    for (int o = 1; o < 32; o <<= 1) {
        int v = __shfl_up_sync(0xffffffffu, sc, o);
        int w = __shfl_up_sync(0xffffffffu, st, o);
        if (lane >= o) { sc += v; st += w; }
    }
    int off  = sc - c;
    int toff = st - tiles;
    if (lane < NTYPE) {
        g_offset[lane] = off;
        g_cursor[lane] = off;
        for (int t = 0; t < tiles; t++) g_work[toff + t] = (lane << 8) | t;
    }
    int tot = __shfl_sync(0xffffffffu, st, NTYPE - 1);
    if (lane == 0) g_nwork = tot;
}

__global__ void k_scatter(const int* __restrict__ Q) {
    __shared__ int loc[NTYPE], base[NTYPE];
    int tid = threadIdx.x;
    if (tid < NTYPE) loc[tid] = 0;
    __syncthreads();
    int per = (N_TOK + gridDim.x - 1) / gridDim.x;
    int s = blockIdx.x * per;
    int e = min(s + per, N_TOK);
    for (int i = s + tid; i < e; i += blockDim.x)
        atomicAdd(&loc[Q[i]], 1);
    __syncthreads();
    if (tid < NTYPE) { base[tid] = atomicAdd(&g_cursor[tid], loc[tid]); loc[tid] = 0; }
    __syncthreads();
    for (int i = s + tid; i < e; i += blockDim.x) {
        int t = Q[i];
        g_order[base[t] + atomicAdd(&loc[t], 1)] = i;
    }
}

// Persistent scalar-FFMA GEMM + fused row-norm + argmin + commit-loss
// + idx-tail + fused output-row copy (out row = g_ne[winning code]).
__global__ __launch_bounds__(256, 2) void k_argmin(const float* __restrict__ x,
                                                   const float* __restrict__ emb,
                                                   float* __restrict__ out) {
    __shared__ __align__(16) float As[KC][128];   // [k][token]
    __shared__ __align__(16) float Bs[KC][128];   // [k][code]
    __shared__ int   toks[128];
    __shared__ float snorm[128];
    __shared__ float sen2[128];
    __shared__ int   scodes[128];
    __shared__ int   s_work;
    __shared__ float red[256];

    int tid = threadIdx.x;
    int tx = tid & 15, ty = tid >> 4;   // 16x16 thread grid, 8x8 frags
    int fr = tid >> 1;                  // fill row 0..127
    int fq = tid & 1;                   // fill k-half (16 floats each)
    float local_loss = 0.0f;

    for (;;) {
        if (tid == 0) s_work = atomicAdd(&g_ticket, 1);
        __syncthreads();
        int w = s_work;
        if (w >= g_nwork) break;
        int wk   = g_work[w];
        int type = wk >> 8;
        int row0 = (wk & 255) * 128;
        int cnt  = g_count[type];
        int rows = min(128, cnt - row0);

        if (tid < 128) {
            int r = (tid < rows) ? tid : (rows - 1);
            toks[tid]  = g_order[g_offset[type] + row0 + r];
            snorm[tid] = 0.0f;
            sen2[tid]  = g_en2[type * PER + tid];
        }
        __syncthreads();

        const float* xrow = x   + (size_t)toks[fr] * DIM + fq * 16;
        const float* brow = emb + (size_t)(type * PER + fr) * DIM + fq * 16;

        float acc[8][8];
        #pragma unroll
        for (int i = 0; i < 8; i++)
            #pragma unroll
            for (int j = 0; j < 8; j++) acc[i][j] = 0.0f;

        for (int k0 = 0; k0 < DIM; k0 += KC) {
            // --- fill A + accumulate row sumsq; fill B ---
            float ps = 0.0f;
            #pragma unroll
            for (int u = 0; u < 4; u++) {
                float4 v = *(const float4*)(xrow + k0 + 4 * u);
                ps += v.x*v.x + v.y*v.y + v.z*v.z + v.w*v.w;
                int kb = fq * 16 + 4 * u;
                As[kb+0][fr] = v.x; As[kb+1][fr] = v.y;
                As[kb+2][fr] = v.z; As[kb+3][fr] = v.w;
            }
            atomicAdd(&snorm[fr], ps);
            #pragma unroll
            for (int u = 0; u < 4; u++) {
                float4 v = *(const float4*)(brow + k0 + 4 * u);
                int kb = fq * 16 + 4 * u;
                Bs[kb+0][fr] = v.x; Bs[kb+1][fr] = v.y;
                Bs[kb+2][fr] = v.z; Bs[kb+3][fr] = v.w;
            }
            __syncthreads();

            #pragma unroll
            for (int kk = 0; kk < KC; kk++) {
                float4 a0 = *(const float4*)&As[kk][ty*4];
                float4 a1 = *(const float4*)&As[kk][64 + ty*4];
                float4 b0 = *(const float4*)&Bs[kk][tx*4];
                float4 b1 = *(const float4*)&Bs[kk][64 + tx*4];
                float a[8] = {a0.x,a0.y,a0.z,a0.w,a1.x,a1.y,a1.z,a1.w};
                float b[8] = {b0.x,b0.y,b0.z,b0.w,b1.x,b1.y,b1.z,b1.w};
                #pragma unroll
                for (int i = 0; i < 8; i++)
                    #pragma unroll
                    for (int j = 0; j < 8; j++)
                        acc[i][j] = fmaf(a[i], b[j], acc[i][j]);
            }
            __syncthreads();
        }

        // --- epilogue: argmin + loss + idx tail ---
        #pragma unroll
        for (int i = 0; i < 8; i++) {
            int m = (i < 4) ? (ty*4 + i) : (64 + ty*4 + (i - 4));
            float invn = 1.0f / fmaxf(sqrtf(snorm[m]), 1e-12f);
            float best = FLT_MAX; int bc = 1 << 30;
            #pragma unroll
            for (int j = 0; j < 8; j++) {
                int c = (j < 4) ? (tx*4 + j) : (64 + tx*4 + (j - 4));
                float s = sen2[c] - 2.0f * invn * acc[i][j];
                if (s < best || (s == best && c < bc)) { best = s; bc = c; }
            }
            #pragma unroll
            for (int o = 8; o; o >>= 1) {
                float s2 = __shfl_xor_sync(0xffffffffu, best, o);
                int   c2 = __shfl_xor_sync(0xffffffffu, bc,   o);
                if (s2 < best || (s2 == best && c2 < bc)) { best = s2; bc = c2; }
            }
            if (tx == 0 && m < rows) {
                int tok  = toks[m];
                int code = type * PER + bc;
                scodes[m] = code;
                out[ND + 2 + tok] = (float)code;
                float e2 = sen2[bc];
                // ||q - xn||^2 = 2 - (e2 - best)/sqrt(e2)
                local_loss += 2.0f - (e2 - best) / sqrtf(e2);
            }
        }
        __syncthreads();

        // --- fused finalize: out row = g_ne[code] ---
        if (fr < rows) {
            const float4* src = (const float4*)(g_ne + (size_t)scodes[fr] * DIM) + fq * 64;
            float4*       dst = (float4*)(out + (size_t)toks[fr] * DIM) + fq * 64;
            #pragma unroll 8
            for (int q = 0; q < 64; q++) dst[q] = src[q];
        }
        // loop-top __syncthreads orders copy before smem reuse
    }

    red[tid] = local_loss;
    __syncthreads();
    for (int s = 128; s; s >>= 1) {
        if (tid < s) red[tid] += red[tid + s];
        __syncthreads();
    }
    if (tid == 0 && red[0] != 0.0f) atomicAdd(&g_diff_acc, (double)red[0]);
}

__global__ void k_gather_se(const int* __restrict__ samp) {
    int b = blockIdx.x;
    int s = samp[b];
    int t = threadIdx.x;
    ((float4*)(g_se + (size_t)b * DIM))[t] =
        ((const float4*)(g_ne + (size_t)s * DIM))[t];
    if (t == 0) g_slab[b] = s / PER;
}

__global__ __launch_bounds__(256) void k_uloss(float* __restrict__ out) {
    int i = blockIdx.x;
    __shared__ float si[DIM];
    __shared__ float wsum[8], wpos[8];
    int tid = threadIdx.x;
    if (tid < 128) ((float4*)si)[tid] = ((const float4*)(g_se + (size_t)i * DIM))[tid];
    __syncthreads();
    int lab_i = g_slab[i];
    int w = tid >> 5, lane = tid & 31;
    float sum = 0.0f, pos = 0.0f;
    for (int j = w; j < SAMP; j += 8) {
        const float* vj = g_se + (size_t)j * DIM;
        float p = 0.0f;
        #pragma unroll 4
        for (int d = lane; d < DIM; d += 32) p = fmaf(si[d], vj[d], p);
        #pragma unroll
        for (int o = 16; o; o >>= 1) p += __shfl_xor_sync(0xffffffffu, p, o);
        if (lane == 0 && j != i) {
            float e = expf(p / TEMP);
            sum += e;
            if (g_slab[j] == lab_i) pos += e;
        }
    }
    if (lane == 0) { wsum[w] = sum; wpos[w] = pos; }
    __syncthreads();
    if (tid == 0) {
        float S = 0.0f, P = 0.0f;
        #pragma unroll
        for (int k = 0; k < 8; k++) { S += wsum[k]; P += wpos[k]; }
        atomicAdd(&g_uloss_acc, (double)(-logf(P / S)));
        __threadfence();
        int d = atomicAdd(&g_udone, 1);
        if (d == SAMP - 1) {
            double u = atomicAdd(&g_uloss_acc, 0.0);
            out[ND]     = (float)((1.0 + (double)COMMIT) * g_diff_acc / (double)ND);
            out[ND + 1] = (float)(u / (double)SAMP);
        }
    }
}

// -------- launch --------
extern "C" void kernel_launch(void* const* d_in, const int* in_sizes, int n_in,
                              void* d_out, int out_size) {
    const float* x    = (const float*)d_in[0];
    const float* emb  = (const float*)d_in[1];
    const int*   Q    = (const int*)d_in[2];
    const int*   samp = (const int*)d_in[3];
    float* out = (float*)d_out;

    k_init<<<1, 32>>>();
    k_norm_emb<<<NCODE, 128>>>(emb);
    k_hist<<<64, 256>>>(Q);
    k_scan<<<1, 32>>>();
    k_scatter<<<64, 256>>>(Q);
    k_argmin<<<296, 256>>>(x, emb, out);
    k_gather_se<<<SAMP, 128>>>(samp);
    k_uloss<<<SAMP, 256>>>(out);
}